// round 8
// baseline (speedup 1.0000x reference)
#include <cuda_runtime.h>
#include <cuda_bf16.h>
#include <cstdint>

// Problem constants (fixed by the dataset)
#define Bsz 8
#define Nn  512
#define Dd  256
#define Ee  16384

// Scratch: AB_bf[b*N + n][0:256] = F@W1_top + b1, [256:512] = F@W1_bot  (4 MB)
__device__ __nv_bfloat16 g_AB[(size_t)Bsz * Nn * 512];

__device__ __forceinline__ uint32_t smem_u32(const void* p) {
    uint32_t a;
    asm("{ .reg .u64 t; cvta.to.shared.u64 t, %1; cvt.u32.u64 %0, t; }"
        : "=r"(a) : "l"(p));
    return a;
}

__device__ __forceinline__ void mma_bf16(
    float c[4], uint32_t a0, uint32_t a1, uint32_t a2, uint32_t a3,
    uint32_t b0, uint32_t b1)
{
    asm volatile(
        "mma.sync.aligned.m16n8k16.row.col.f32.bf16.bf16.f32 "
        "{%0,%1,%2,%3}, {%4,%5,%6,%7}, {%8,%9}, {%0,%1,%2,%3};"
        : "+f"(c[0]), "+f"(c[1]), "+f"(c[2]), "+f"(c[3])
        : "r"(a0), "r"(a1), "r"(a2), "r"(a3), "r"(b0), "r"(b1));
}

// ---------------------------------------------------------------------------
// Phase 1: tensor GEMM  AB(4096 x 512) = F(4096 x 256) @ Wc(256 x 512), bf16.
//   Wc[k][j] = W1[k*256 + j]             (j < 256)
//            = W1[(256+k)*256 + (j-256)] (j >= 256)
// CTA tile M=128 x N=64, K chunked by 32, register double-buffered loads.
// A in smem as packed bf16 k-pairs (stride 20 words, conflict-free LDS.32).
// B in smem as [k][n] bf16 rows (stride 72, conflict-free ldmatrix.x2.trans).
// Epilogue: +b1 (cols<256), bf16 store. Prologue: zero a slice of `out`.
// ---------------------------------------------------------------------------
#define A_STR 20   /* uint32 words per A row: 16 data + 4 pad */
#define B_STR 72   /* bf16 elems per B row: 64 data + 8 pad */

__global__ __launch_bounds__(256) void gemm_tc_kernel(
    const float* __restrict__ F, const float* __restrict__ W1,
    const float* __restrict__ b1v, __nv_bfloat16* __restrict__ AB,
    float* __restrict__ outz)
{
    __shared__ uint32_t      As2[128 * A_STR];   // 10240 B
    __shared__ __nv_bfloat16 Bs2[32 * B_STR];    //  4608 B

    const int tid  = threadIdx.x;
    const int wid  = tid >> 5;
    const int lane = tid & 31;
    const int lq   = lane >> 2;   // 0..7
    const int lr   = lane & 3;    // 0..3

    const int n0 = blockIdx.x * 64;    // 0..448
    const int m0 = blockIdx.y * 128;   // 0..3968

    const int wm = wid >> 1;          // 0..3  (m quadrant, 32 rows)
    const int wn = wid & 1;           // 0..1  (n half, 32 cols)

    // ---- Zero the final output (replaces cudaMemsetAsync; overlaps loads)
    {
        const int gtid = (blockIdx.y * 8 + blockIdx.x) * 256 + tid; // 0..65535
        const float4 z = make_float4(0.f, 0.f, 0.f, 0.f);
#pragma unroll
        for (int i = 0; i < 8; i++)
            *(float4*)(outz + (((size_t)(i * 65536 + gtid)) << 2)) = z;
    }

    const float* Wsrc = (n0 < 256) ? (W1 + n0) : (W1 + 256 * 256 + (n0 - 256));
    const uint32_t bs_base = smem_u32(Bs2);

    // ---- Prologue: load chunk kc=0 into registers
    float4 a4[4], b4[2];
#pragma unroll
    for (int it = 0; it < 4; it++) {
        const int idx = it * 256 + tid;
        a4[it] = *(const float4*)(F + (size_t)(m0 + (idx >> 3)) * 256 + (idx & 7) * 4);
    }
#pragma unroll
    for (int it = 0; it < 2; it++) {
        const int idx = it * 256 + tid;
        b4[it] = *(const float4*)(Wsrc + (size_t)(idx >> 4) * 256 + (idx & 15) * 4);
    }

    float c[2][4][4] = {};            // [m-tile][n-tile][frag]

#pragma unroll 1
    for (int kc = 0; kc < 256; kc += 32) {
        // ---- Store current chunk regs -> smem (cvt to bf16 pairs)
#pragma unroll
        for (int it = 0; it < 4; it++) {
            const int idx = it * 256 + tid;
            __nv_bfloat162 h0 = __floats2bfloat162_rn(a4[it].x, a4[it].y);
            __nv_bfloat162 h1 = __floats2bfloat162_rn(a4[it].z, a4[it].w);
            uint32_t* d = &As2[(idx >> 3) * A_STR + (idx & 7) * 2];
            d[0] = *(uint32_t*)&h0;
            d[1] = *(uint32_t*)&h1;
        }
#pragma unroll
        for (int it = 0; it < 2; it++) {
            const int idx = it * 256 + tid;
            __nv_bfloat162 h0 = __floats2bfloat162_rn(b4[it].x, b4[it].y);
            __nv_bfloat162 h1 = __floats2bfloat162_rn(b4[it].z, b4[it].w);
            uint32_t* d = (uint32_t*)&Bs2[(idx >> 4) * B_STR + (idx & 15) * 4];
            d[0] = *(uint32_t*)&h0;
            d[1] = *(uint32_t*)&h1;
        }
        __syncthreads();

        // ---- Prefetch next chunk (overlaps with MMA below)
        if (kc < 224) {
            const int kn = kc + 32;
#pragma unroll
            for (int it = 0; it < 4; it++) {
                const int idx = it * 256 + tid;
                a4[it] = *(const float4*)(F + (size_t)(m0 + (idx >> 3)) * 256 + kn + (idx & 7) * 4);
            }
#pragma unroll
            for (int it = 0; it < 2; it++) {
                const int idx = it * 256 + tid;
                b4[it] = *(const float4*)(Wsrc + (size_t)(kn + (idx >> 4)) * 256 + (idx & 15) * 4);
            }
        }

        // ---- Compute: 2 k-steps of 16
#pragma unroll
        for (int ks = 0; ks < 2; ks++) {
            const int kp0 = ks * 8;   // k-pair base (k0 = 16*ks)
            uint32_t a[2][4];
#pragma unroll
            for (int i = 0; i < 2; i++) {
                const int rb = (wm * 32 + i * 16 + lq) * A_STR + kp0 + lr;
                a[i][0] = As2[rb];
                a[i][1] = As2[rb + 8 * A_STR];
                a[i][2] = As2[rb + 4];
                a[i][3] = As2[rb + 8 * A_STR + 4];
            }
            uint32_t b[4][2];
#pragma unroll
            for (int j = 0; j < 4; j++) {
                const int ncol = wn * 32 + j * 8;
                const uint32_t addr = bs_base +
                    (uint32_t)(((ks * 16 + (lane & 15)) * B_STR + ncol) * 2);
                asm volatile(
                    "ldmatrix.sync.aligned.m8n8.x2.trans.shared.b16 {%0,%1}, [%2];"
                    : "=r"(b[j][0]), "=r"(b[j][1]) : "r"(addr));
            }
#pragma unroll
            for (int i = 0; i < 2; i++)
#pragma unroll
                for (int j = 0; j < 4; j++)
                    mma_bf16(c[i][j], a[i][0], a[i][1], a[i][2], a[i][3],
                             b[j][0], b[j][1]);
        }
        __syncthreads();
    }

    // ---- Epilogue: add b1 (cols<256 only), pack to bf16, store.
    float2 bias[4];
#pragma unroll
    for (int j = 0; j < 4; j++) {
        const int col = n0 + wn * 32 + j * 8 + 2 * lr;
        bias[j] = (n0 < 256) ? *(const float2*)(b1v + col)
                             : make_float2(0.f, 0.f);
    }
#pragma unroll
    for (int i = 0; i < 2; i++) {
        const int rbase = m0 + wm * 32 + i * 16 + lq;
#pragma unroll
        for (int j = 0; j < 4; j++) {
            const int col = n0 + wn * 32 + j * 8 + 2 * lr;
            float2 v0 = make_float2(c[i][j][0] + bias[j].x, c[i][j][1] + bias[j].y);
            float2 v1 = make_float2(c[i][j][2] + bias[j].x, c[i][j][3] + bias[j].y);
            *(__nv_bfloat162*)(AB + (size_t)rbase * 512 + col) =
                __float22bfloat162_rn(v0);
            *(__nv_bfloat162*)(AB + (size_t)(rbase + 8) * 512 + col) =
                __float22bfloat162_rn(v1);
        }
    }
}

// ---------------------------------------------------------------------------
// Phase 2: per-(b,e) edge MLP tail + scatter.  AB is bf16, b1 pre-folded.
// One warp per 2 edges (low regs -> high occupancy). bf16x2 add/relu, exact
// bf16->fp32 unpack, fp32 dot. 5-shfl dual-edge reduce, parallel sigmoid.
// ---------------------------------------------------------------------------
__global__ __launch_bounds__(256) void edge_kernel(
    const __nv_bfloat16* __restrict__ AB,
    const float* __restrict__ W2,
    const float* __restrict__ b2,
    const void* __restrict__ edge_raw,
    float* __restrict__ out)
{
    const int tid  = threadIdx.x;
    const int warp = tid >> 5;
    const int lane = tid & 31;
    const int ch   = lane * 8;          // 8 channels per lane

    const int*       e32 = (const int*)edge_raw;
    const long long* e64 = (const long long*)edge_raw;

    // In-warp dtype detection: int64 buffer has all odd words zero.
    int vdet = e32[2 * lane + 1];
    unsigned any = __ballot_sync(0xffffffffu, vdet != 0);
    const bool is64 = (any == 0u);

    float w[8];
    *(float4*)&w[0] = *(const float4*)(W2 + ch);
    *(float4*)&w[4] = *(const float4*)(W2 + ch + 4);
    const float b2v = b2[0];

    const int wslot = blockIdx.x * 8 + warp;  // 0..65535

    uint32_t key[2], aoff[2], boff[2];
#pragma unroll
    for (int r = 0; r < 2; r++) {
        const int g = wslot * 2 + r;            // 0..131071  (b,e) pair
        const int b = g >> 14;                  // E = 16384
        const int e = g & (Ee - 1);
        int src, dst;
        if (is64) {
            src = (int)e64[e];
            dst = (int)e64[Ee + e];
        } else {
            src = e32[e];
            dst = e32[Ee + e];
        }
        key[r]  = ((uint32_t)b << 18) | ((uint32_t)src << 9) | (uint32_t)dst;
        aoff[r] = (((uint32_t)(b * Nn + src)) << 9) + ch;
        boff[r] = (((uint32_t)(b * Nn + dst)) << 9) + 256 + ch;
    }

    // Issue all 4 row-gathers up front
    uint4 av[2], bv[2];
#pragma unroll
    for (int r = 0; r < 2; r++) {
        av[r] = *(const uint4*)(AB + aoff[r]);
        bv[r] = *(const uint4*)(AB + boff[r]);
    }

    const __nv_bfloat162 z2 = __float2bfloat162_rn(0.f);
    float acc[2];
#pragma unroll
    for (int r = 0; r < 2; r++) {
        const __nv_bfloat162* ap = (const __nv_bfloat162*)&av[r];
        const __nv_bfloat162* bp = (const __nv_bfloat162*)&bv[r];
        float a = 0.f;
#pragma unroll
        for (int p = 0; p < 4; p++) {
            __nv_bfloat162 h = __hmax2(__hadd2(ap[p], bp[p]), z2);
            float2 f = __bfloat1622float2(h);
            a = fmaf(f.x, w[2 * p], a);
            a = fmaf(f.y, w[2 * p + 1], a);
        }
        acc[r] = a;
    }

    // ---- Dual-edge reduction: 5 shfls. After stage 1, half h holds edge h.
    const bool hi16 = (lane & 16) != 0;
    float send = hi16 ? acc[0] : acc[1];
    float recv = __shfl_xor_sync(0xffffffffu, send, 16);
    float t    = (hi16 ? acc[1] : acc[0]) + recv;

    t += __shfl_xor_sync(0xffffffffu, t, 8);
    t += __shfl_xor_sync(0xffffffffu, t, 4);
    t += __shfl_xor_sync(0xffffffffu, t, 2);
    t += __shfl_xor_sync(0xffffffffu, t, 1);

    const uint32_t k = hi16 ? key[1] : key[0];
    const float s = 1.0f / (1.0f + expf(-(t + b2v)));
    if ((lane & 15) == 0)
        out[k] = s;
}

// ---------------------------------------------------------------------------
extern "C" void kernel_launch(void* const* d_in, const int* in_sizes, int n_in,
                              void* d_out, int out_size)
{
    const float* features = (const float*)d_in[0];   // (8,512,256)
    const float* W1       = (const float*)d_in[1];   // (512,256)
    const float* b1       = (const float*)d_in[2];   // (256)
    const float* W2       = (const float*)d_in[3];   // (256,1)
    const float* b2       = (const float*)d_in[4];   // (1)
    const void*  edge     = d_in[5];                 // (2,16384) int32 or int64
    float*       out      = (float*)d_out;           // (8,512,512)

    __nv_bfloat16* AB;
    cudaGetSymbolAddress((void**)&AB, g_AB);

    // Phase 1: AB = F @ Wc (mma.sync bf16) + fold b1 + zero `out` in prologue
    dim3 ggrid(8, 32);   // N-tiles x M-tiles
    gemm_tc_kernel<<<ggrid, 256>>>(features, W1, b1, AB, out);

    // Phase 2: edge MLP tail + scatter (2 edges per warp)
    edge_kernel<<<8192, 256>>>(AB, W2, b2, edge, out);
}

// round 10
// speedup vs baseline: 1.0743x; 1.0743x over previous
#include <cuda_runtime.h>
#include <cuda_bf16.h>
#include <cstdint>

// Problem constants (fixed by the dataset)
#define Bsz 8
#define Nn  512
#define Dd  256
#define Ee  16384

// Scratch buffers (device globals; no allocation allowed)
__device__ __nv_bfloat16 g_AB[(size_t)Bsz * Nn * 512];  // 4 MB  (GEMM out + b1)
__device__ __nv_bfloat16 g_Fb[(size_t)Bsz * Nn * 256];  // 2 MB  (features, bf16)
__device__ __nv_bfloat16 g_Wc[(size_t)256 * 512];       // 256KB (concat W1, bf16)

__device__ __forceinline__ uint32_t smem_u32(const void* p) {
    uint32_t a;
    asm("{ .reg .u64 t; cvta.to.shared.u64 t, %1; cvt.u32.u64 %0, t; }"
        : "=r"(a) : "l"(p));
    return a;
}

__device__ __forceinline__ void cp16(uint32_t dst, const void* src) {
    asm volatile("cp.async.cg.shared.global [%0], [%1], 16;"
                 :: "r"(dst), "l"(src));
}

__device__ __forceinline__ void mma_bf16(
    float c[4], uint32_t a0, uint32_t a1, uint32_t a2, uint32_t a3,
    uint32_t b0, uint32_t b1)
{
    asm volatile(
        "mma.sync.aligned.m16n8k16.row.col.f32.bf16.bf16.f32 "
        "{%0,%1,%2,%3}, {%4,%5,%6,%7}, {%8,%9}, {%0,%1,%2,%3};"
        : "+f"(c[0]), "+f"(c[1]), "+f"(c[2]), "+f"(c[3])
        : "r"(a0), "r"(a1), "r"(a2), "r"(a3), "r"(b0), "r"(b1));
}

// ---------------------------------------------------------------------------
// Phase 0: convert F -> bf16 (g_Fb), W1 -> concat bf16 (g_Wc), zero output.
//   Wc[k][j] = W1[k][j] (j<256) ; W1[256+k][j-256] (j>=256)
// grid 1024 x 256: thread t handles F float4 #t; t<32768 also one Wc float4;
// every thread zeroes 2 float4 of out (524288 float4 total / 262144 threads).
// ---------------------------------------------------------------------------
__global__ __launch_bounds__(256) void conv_kernel(
    const float* __restrict__ F, const float* __restrict__ W1,
    __nv_bfloat16* __restrict__ Fb, __nv_bfloat16* __restrict__ Wc,
    float* __restrict__ outz)
{
    const int t = blockIdx.x * 256 + threadIdx.x;   // 0..262143

    // F: 262144 float4
    {
        float4 v = *(const float4*)(F + (size_t)t * 4);
        __nv_bfloat162 h0 = __floats2bfloat162_rn(v.x, v.y);
        __nv_bfloat162 h1 = __floats2bfloat162_rn(v.z, v.w);
        uint32_t* d = (uint32_t*)(Fb + (size_t)t * 4);
        d[0] = *(uint32_t*)&h0;
        d[1] = *(uint32_t*)&h1;
    }

    // Wc: 32768 float4 (256 rows x 128 float4)
    if (t < 32768) {
        const int k  = t >> 7;
        const int j4 = t & 127;
        const float* src = (j4 < 64)
            ? (W1 + (size_t)k * 256 + j4 * 4)
            : (W1 + (size_t)(256 + k) * 256 + (j4 - 64) * 4);
        float4 v = *(const float4*)src;
        __nv_bfloat162 h0 = __floats2bfloat162_rn(v.x, v.y);
        __nv_bfloat162 h1 = __floats2bfloat162_rn(v.z, v.w);
        uint32_t* d = (uint32_t*)(Wc + (size_t)k * 512 + j4 * 4);
        d[0] = *(uint32_t*)&h0;
        d[1] = *(uint32_t*)&h1;
    }

    // Zero output: 524288 float4 / 262144 threads = 2 each
    const float4 z = make_float4(0.f, 0.f, 0.f, 0.f);
#pragma unroll
    for (int i = 0; i < 2; i++)
        *(float4*)(outz + (((size_t)(i * 262144 + t)) << 2)) = z;
}

// ---------------------------------------------------------------------------
// Phase 1: tensor GEMM  AB(4096 x 512) = Fb(4096 x 256) @ Wc(256 x 512), bf16.
// CTA tile M=128 x N=64, K chunked by 32, cp.async double-buffered smem.
// A smem: packed bf16 k-pairs, stride 20 words. B smem: [k][n], stride 72.
// Epilogue: +b1 (cols<256), bf16 store to g_AB.
// ---------------------------------------------------------------------------
#define A_STR 20   /* uint32 words per A row: 16 data + 4 pad */
#define B_STR 72   /* bf16 elems per B row: 64 data + 8 pad */

__global__ __launch_bounds__(256) void gemm_tc_kernel(
    const __nv_bfloat16* __restrict__ Fb, const __nv_bfloat16* __restrict__ Wc,
    const float* __restrict__ b1v, __nv_bfloat16* __restrict__ AB)
{
    __shared__ alignas(16) uint32_t      As2[2][128 * A_STR];   // 2 x 10240 B
    __shared__ alignas(16) __nv_bfloat16 Bs2[2][32 * B_STR];    // 2 x  4608 B

    const int tid  = threadIdx.x;
    const int wid  = tid >> 5;
    const int lane = tid & 31;
    const int lq   = lane >> 2;   // 0..7
    const int lr   = lane & 3;    // 0..3

    const int n0 = blockIdx.x * 64;    // 0..448
    const int m0 = blockIdx.y * 128;   // 0..3968

    const int wm = wid >> 1;          // 0..3  (m quadrant, 32 rows)
    const int wn = wid & 1;           // 0..1  (n half, 32 cols)

    const uint32_t as_base[2] = { smem_u32(&As2[0][0]), smem_u32(&As2[1][0]) };
    const uint32_t bs_base[2] = { smem_u32(&Bs2[0][0]), smem_u32(&Bs2[1][0]) };

    // Per-thread cp.async assignments
    //   A: ops o = tid, tid+256 : row = o>>2, seg = o&3  (512 x 16B)
    //   B: op  o = tid          : row = o>>3, seg = o&7  (256 x 16B)
    const int a_row0 = tid >> 2,         a_seg0 = tid & 3;
    const int a_row1 = (tid + 256) >> 2, a_seg1 = tid & 3;
    const int b_row  = tid >> 3,         b_seg  = tid & 7;

    #define ISSUE_CHUNK(buf, kc_) do {                                         \
        cp16(as_base[buf] + (uint32_t)(a_row0 * 80 + a_seg0 * 16),             \
             Fb + (size_t)(m0 + a_row0) * 256 + (kc_) + a_seg0 * 8);           \
        cp16(as_base[buf] + (uint32_t)(a_row1 * 80 + a_seg1 * 16),             \
             Fb + (size_t)(m0 + a_row1) * 256 + (kc_) + a_seg1 * 8);           \
        cp16(bs_base[buf] + (uint32_t)(b_row * 144 + b_seg * 16),              \
             Wc + (size_t)((kc_) + b_row) * 512 + n0 + b_seg * 8);             \
        asm volatile("cp.async.commit_group;" ::: "memory");                   \
    } while (0)

    ISSUE_CHUNK(0, 0);

    float c[2][4][4] = {};            // [m-tile][n-tile][frag]

#pragma unroll 1
    for (int i = 0; i < 8; i++) {
        const int buf = i & 1;
        if (i < 7) {
            ISSUE_CHUNK(buf ^ 1, (i + 1) * 32);
            asm volatile("cp.async.wait_group 1;" ::: "memory");
        } else {
            asm volatile("cp.async.wait_group 0;" ::: "memory");
        }
        __syncthreads();

        const uint32_t* Asb = &As2[buf][0];
        const uint32_t  bsb = bs_base[buf];

#pragma unroll
        for (int ks = 0; ks < 2; ks++) {
            const int kp0 = ks * 8;   // k-pair base (k0 = 16*ks)
            uint32_t a[2][4];
#pragma unroll
            for (int ii = 0; ii < 2; ii++) {
                const int rb = (wm * 32 + ii * 16 + lq) * A_STR + kp0 + lr;
                a[ii][0] = Asb[rb];
                a[ii][1] = Asb[rb + 8 * A_STR];
                a[ii][2] = Asb[rb + 4];
                a[ii][3] = Asb[rb + 8 * A_STR + 4];
            }
            uint32_t b[4][2];
#pragma unroll
            for (int j = 0; j < 4; j++) {
                const int ncol = wn * 32 + j * 8;
                const uint32_t addr = bsb +
                    (uint32_t)(((ks * 16 + (lane & 15)) * B_STR + ncol) * 2);
                asm volatile(
                    "ldmatrix.sync.aligned.m8n8.x2.trans.shared.b16 {%0,%1}, [%2];"
                    : "=r"(b[j][0]), "=r"(b[j][1]) : "r"(addr));
            }
#pragma unroll
            for (int ii = 0; ii < 2; ii++)
#pragma unroll
                for (int j = 0; j < 4; j++)
                    mma_bf16(c[ii][j], a[ii][0], a[ii][1], a[ii][2], a[ii][3],
                             b[j][0], b[j][1]);
        }
        __syncthreads();
    }

    // ---- Epilogue: add b1 (cols<256 only), pack to bf16, store.
    float2 bias[4];
#pragma unroll
    for (int j = 0; j < 4; j++) {
        const int col = n0 + wn * 32 + j * 8 + 2 * lr;
        bias[j] = (n0 < 256) ? *(const float2*)(b1v + col)
                             : make_float2(0.f, 0.f);
    }
#pragma unroll
    for (int i = 0; i < 2; i++) {
        const int rbase = m0 + wm * 32 + i * 16 + lq;
#pragma unroll
        for (int j = 0; j < 4; j++) {
            const int col = n0 + wn * 32 + j * 8 + 2 * lr;
            float2 v0 = make_float2(c[i][j][0] + bias[j].x, c[i][j][1] + bias[j].y);
            float2 v1 = make_float2(c[i][j][2] + bias[j].x, c[i][j][3] + bias[j].y);
            *(__nv_bfloat162*)(AB + (size_t)rbase * 512 + col) =
                __float22bfloat162_rn(v0);
            *(__nv_bfloat162*)(AB + (size_t)(rbase + 8) * 512 + col) =
                __float22bfloat162_rn(v1);
        }
    }
}

// ---------------------------------------------------------------------------
// Phase 2: edge MLP tail + scatter — R7 version (measured best: 15.2us).
// One warp per 4 edges. bf16x2 add/relu, fp32 dot, 6-shfl multi-edge reduce.
// ---------------------------------------------------------------------------
__global__ __launch_bounds__(256) void edge_kernel(
    const __nv_bfloat16* __restrict__ AB,
    const float* __restrict__ W2,
    const float* __restrict__ b2,
    const void* __restrict__ edge_raw,
    float* __restrict__ out)
{
    const int tid  = threadIdx.x;
    const int warp = tid >> 5;
    const int lane = tid & 31;
    const int ch   = lane * 8;          // 8 channels per lane

    const int*       e32 = (const int*)edge_raw;
    const long long* e64 = (const long long*)edge_raw;

    // In-warp dtype detection: int64 buffer has all odd words zero.
    int vdet = e32[2 * lane + 1];
    unsigned any = __ballot_sync(0xffffffffu, vdet != 0);
    const bool is64 = (any == 0u);

    float w[8];
    *(float4*)&w[0] = *(const float4*)(W2 + ch);
    *(float4*)&w[4] = *(const float4*)(W2 + ch + 4);
    const float b2v = b2[0];

    const int wslot = blockIdx.x * 8 + warp;  // 0..32767

    uint32_t key[4], aoff[4], boff[4];
#pragma unroll
    for (int r = 0; r < 4; r++) {
        const int g = wslot * 4 + r;            // 0..131071  (b,e) pair
        const int b = g >> 14;                  // E = 16384
        const int e = g & (Ee - 1);
        int src, dst;
        if (is64) {
            src = (int)e64[e];
            dst = (int)e64[Ee + e];
        } else {
            src = e32[e];
            dst = e32[Ee + e];
        }
        key[r]  = ((uint32_t)b << 18) | ((uint32_t)src << 9) | (uint32_t)dst;
        aoff[r] = (((uint32_t)(b * Nn + src)) << 9) + ch;
        boff[r] = (((uint32_t)(b * Nn + dst)) << 9) + 256 + ch;
    }

    // Issue all 8 row-gathers up front (MLP=8)
    uint4 av[4], bv[4];
#pragma unroll
    for (int r = 0; r < 4; r++) {
        av[r] = *(const uint4*)(AB + aoff[r]);
        bv[r] = *(const uint4*)(AB + boff[r]);
    }

    const __nv_bfloat162 z2 = __float2bfloat162_rn(0.f);
    float acc[4];
#pragma unroll
    for (int r = 0; r < 4; r++) {
        const __nv_bfloat162* ap = (const __nv_bfloat162*)&av[r];
        const __nv_bfloat162* bp = (const __nv_bfloat162*)&bv[r];
        float a = 0.f;
#pragma unroll
        for (int p = 0; p < 4; p++) {
            __nv_bfloat162 h = __hmax2(__hadd2(ap[p], bp[p]), z2);
            float2 f = __bfloat1622float2(h);
            a = fmaf(f.x, w[2 * p], a);
            a = fmaf(f.y, w[2 * p + 1], a);
        }
        acc[r] = a;
    }

    // ---- Multi-edge reduction: 6 shfls reduce all 4 edges.
    const bool hi16 = (lane & 16) != 0;
    float send, recv, sA, sB, t;

    send = hi16 ? acc[0] : acc[2];
    recv = __shfl_xor_sync(0xffffffffu, send, 16);
    sA   = (hi16 ? acc[2] : acc[0]) + recv;   // lanes<16: e0, lanes>=16: e2

    send = hi16 ? acc[1] : acc[3];
    recv = __shfl_xor_sync(0xffffffffu, send, 16);
    sB   = (hi16 ? acc[3] : acc[1]) + recv;   // lanes<16: e1, lanes>=16: e3

    const bool hi8 = (lane & 8) != 0;
    send = hi8 ? sA : sB;
    recv = __shfl_xor_sync(0xffffffffu, send, 8);
    t    = (hi8 ? sB : sA) + recv;            // group g holds edge g

    t += __shfl_xor_sync(0xffffffffu, t, 4);
    t += __shfl_xor_sync(0xffffffffu, t, 2);
    t += __shfl_xor_sync(0xffffffffu, t, 1);

    const int g = lane >> 3;
    const uint32_t k = (g & 2) ? ((g & 1) ? key[3] : key[2])
                               : ((g & 1) ? key[1] : key[0]);
    const float s = 1.0f / (1.0f + expf(-(t + b2v)));
    if ((lane & 7) == 0)
        out[k] = s;
}

// ---------------------------------------------------------------------------
extern "C" void kernel_launch(void* const* d_in, const int* in_sizes, int n_in,
                              void* d_out, int out_size)
{
    const float* features = (const float*)d_in[0];   // (8,512,256)
    const float* W1       = (const float*)d_in[1];   // (512,256)
    const float* b1       = (const float*)d_in[2];   // (256)
    const float* W2       = (const float*)d_in[3];   // (256,1)
    const float* b2       = (const float*)d_in[4];   // (1)
    const void*  edge     = d_in[5];                 // (2,16384) int32 or int64
    float*       out      = (float*)d_out;           // (8,512,512)

    __nv_bfloat16 *AB, *Fb, *Wc;
    cudaGetSymbolAddress((void**)&AB, g_AB);
    cudaGetSymbolAddress((void**)&Fb, g_Fb);
    cudaGetSymbolAddress((void**)&Wc, g_Wc);

    // Phase 0: convert inputs to bf16 + zero output
    conv_kernel<<<1024, 256>>>(features, W1, Fb, Wc, out);

    // Phase 1: AB = Fb @ Wc (mma.sync bf16, cp.async pipeline) + fold b1
    dim3 ggrid(8, 32);   // N-tiles x M-tiles
    gemm_tc_kernel<<<ggrid, 256>>>(Fb, Wc, b1, AB);

    // Phase 2: edge MLP tail + scatter (4 edges per warp)
    edge_kernel<<<4096, 256>>>(AB, W2, b2, edge, out);
}